// round 12
// baseline (speedup 1.0000x reference)
#include <cuda_runtime.h>
#include <cuda_bf16.h>

#define N_NODES 50000
#define N_EDGES 800000
#define F_IN    512
#define F_HID   256
#define F_OUT   128

#define SCAN_BLOCKS 64           // 64 * 1024 >= N_NODES

// Scratch
__device__ float g_H0[(size_t)N_NODES * F_HID];
__device__ float g_H1[(size_t)N_NODES * F_HID];
__device__ float g_H2[(size_t)N_NODES * F_OUT];
__device__ int   g_deg[N_NODES];
__device__ int   g_part[N_NODES];
__device__ int   g_bsum[SCAN_BLOCKS];
__device__ int   g_offsets[N_NODES + 1];
__device__ int   g_cursor[N_NODES];
__device__ int   g_ssrc[N_EDGES];
__device__ float g_sw[N_EDGES];

// ---------------------------------------------------------------------------
// CSR build kernels
// ---------------------------------------------------------------------------
__global__ void zero_deg_kernel() {
    int i = blockIdx.x * blockDim.x + threadIdx.x;
    if (i < N_NODES) g_deg[i] = 0;
}

__global__ void hist_kernel(const int* __restrict__ dst) {
    int e = blockIdx.x * blockDim.x + threadIdx.x;
    if (e < N_EDGES) atomicAdd(&g_deg[dst[e]], 1);
}

__global__ __launch_bounds__(1024)
void scan_blocks_kernel() {
    __shared__ int sm[1024];
    int tid = threadIdx.x;
    int i = blockIdx.x * 1024 + tid;
    int v = (i < N_NODES) ? g_deg[i] : 0;
    sm[tid] = v;
    __syncthreads();
    #pragma unroll
    for (int d = 1; d < 1024; d <<= 1) {
        int t = (tid >= d) ? sm[tid - d] : 0;
        __syncthreads();
        sm[tid] += t;
        __syncthreads();
    }
    if (i < N_NODES) g_part[i] = sm[tid] - v;       // exclusive within block
    if (tid == 1023) g_bsum[blockIdx.x] = sm[1023]; // raw block total
}

// add_off with inline bsum prefix (each 256-thread block lies inside one
// 1024-segment, so the segment index is block-uniform).
__global__ void add_off_kernel() {
    __shared__ int s_pref;
    int seg = blockIdx.x >> 2;
    if (threadIdx.x == 0) {
        int p = 0;
        for (int j = 0; j < seg; j++) p += g_bsum[j];
        s_pref = p;
    }
    __syncthreads();
    int i = blockIdx.x * 256 + threadIdx.x;
    if (i < N_NODES) {
        int off = g_part[i] + s_pref;
        g_offsets[i] = off;
        g_cursor[i]  = off;
    }
    if (i == 0) g_offsets[N_NODES] = N_EDGES;
}

__global__ void fill_kernel(const int* __restrict__ src,
                            const int* __restrict__ dst,
                            const float* __restrict__ w) {
    int e = blockIdx.x * blockDim.x + threadIdx.x;
    if (e >= N_EDGES) return;
    int d = dst[e];
    int pos = atomicAdd(&g_cursor[d], 1);
    g_ssrc[pos] = src[e];
    g_sw[pos]   = w[e];
}

// ---------------------------------------------------------------------------
// CSR SpMM: warp per node, register accumulation, one coalesced store.
// ---------------------------------------------------------------------------
template<int F>
__global__ __launch_bounds__(256)
void spmm_csr_kernel(const float* __restrict__ x, float* __restrict__ y) {
    int node = (blockIdx.x * 256 + threadIdx.x) >> 5;
    if (node >= N_NODES) return;
    int lane = threadIdx.x & 31;

    int beg = g_offsets[node];
    int end = g_offsets[node + 1];

    float4 acc0 = make_float4(0.f, 0.f, 0.f, 0.f);
    float4 acc1 = make_float4(0.f, 0.f, 0.f, 0.f);   // used only if F==256

    for (int j = beg; j < end; j++) {
        int s    = __ldg(&g_ssrc[j]);
        float wv = __ldg(&g_sw[j]);
        const float4* xr = (const float4*)(x + (size_t)s * F);
        float4 v0 = __ldg(&xr[lane]);
        acc0.x = fmaf(wv, v0.x, acc0.x);
        acc0.y = fmaf(wv, v0.y, acc0.y);
        acc0.z = fmaf(wv, v0.z, acc0.z);
        acc0.w = fmaf(wv, v0.w, acc0.w);
        if (F == 256) {
            float4 v1 = __ldg(&xr[lane + 32]);
            acc1.x = fmaf(wv, v1.x, acc1.x);
            acc1.y = fmaf(wv, v1.y, acc1.y);
            acc1.z = fmaf(wv, v1.z, acc1.z);
            acc1.w = fmaf(wv, v1.w, acc1.w);
        }
    }

    float4* yr = (float4*)(y + (size_t)node * F);
    yr[lane] = acc0;
    if (F == 256) yr[lane + 32] = acc1;
}

// ---------------------------------------------------------------------------
// GEMM helpers (3xBF16 split)
// ---------------------------------------------------------------------------
__device__ __forceinline__ void split_bf16x2(float f0, float f1,
                                             unsigned& hi, unsigned& lo) {
    asm("cvt.rn.bf16x2.f32 %0, %1, %2;" : "=r"(hi) : "f"(f1), "f"(f0));
    float fh0 = __uint_as_float(hi << 16);
    float fh1 = __uint_as_float(hi & 0xFFFF0000u);
    asm("cvt.rn.bf16x2.f32 %0, %1, %2;" : "=r"(lo)
        : "f"(f1 - fh1), "f"(f0 - fh0));
}

__device__ __forceinline__ void mma_bf16(float c[4], const unsigned a[4],
                                         const unsigned b[2]) {
    asm volatile(
        "mma.sync.aligned.m16n8k16.row.col.f32.bf16.bf16.f32 "
        "{%0,%1,%2,%3}, {%4,%5,%6,%7}, {%8,%9}, {%0,%1,%2,%3};"
        : "+f"(c[0]), "+f"(c[1]), "+f"(c[2]), "+f"(c[3])
        : "r"(a[0]), "r"(a[1]), "r"(a[2]), "r"(a[3]), "r"(b[0]), "r"(b[1]));
}

// ---------------------------------------------------------------------------
// 3xBF16 tensor-core GEMM, split-at-store, register-staged double buffer.
// Block 128x64, BK=16, 8 warps (4x2), warp tile 32x32 (2 mtiles x 4 ntiles).
// acc = 32 regs/thread; __launch_bounds__(256,3) targets 3 CTAs/SM.
// Requires N % 64 == 0, K % 16 == 0. M bounds-checked.
// ---------------------------------------------------------------------------
template<bool RELU_A>
__global__ __launch_bounds__(256, 3)
void gemm_tc_kernel(const float* __restrict__ A, const float* __restrict__ B,
                    float* __restrict__ C, int M, int N, int K) {
    constexpr int BM = 128, BK = 16;
    constexpr int AP = 12;    // A pitch in u32 (8 kpairs + pad) — bank-clean
    constexpr int BP = 72;    // B pitch in u32 (64 cols + pad)  — bank-clean
    __shared__ __align__(16) unsigned As_hi[2][BM * AP];
    __shared__ __align__(16) unsigned As_lo[2][BM * AP];
    __shared__ __align__(16) unsigned Bs_hi[2][8 * BP];
    __shared__ __align__(16) unsigned Bs_lo[2][8 * BP];

    const int tid  = threadIdx.x;
    const int lane = tid & 31;
    const int warp = tid >> 5;
    const int g    = lane >> 2;
    const int tig  = lane & 3;
    const int warp_m = warp & 3;    // 0..3 (32 rows each)
    const int warp_n = warp >> 2;   // 0..1 (32 cols each)

    const int row0 = blockIdx.y * BM;
    const int col0 = blockIdx.x * 64;

    const int a_m0 = tid >> 2;          // 0..63 (+64)
    const int a_kq = tid & 3;
    const int b_kp = (tid >> 4) & 7;    // threads 0..127 load B
    const int b_cq = (tid & 15) * 4;

    float acc[2][4][4];
    #pragma unroll
    for (int i = 0; i < 2; i++)
        #pragma unroll
        for (int j = 0; j < 4; j++)
            #pragma unroll
            for (int l = 0; l < 4; l++) acc[i][j][l] = 0.f;

    float4 a_reg[2], b_reg[2];

    auto ldg_tile = [&](int k0) {
        #pragma unroll
        for (int p = 0; p < 2; p++) {
            int m = a_m0 + p * 64;
            int gr = row0 + m;
            if (gr < M)
                a_reg[p] = *(const float4*)(A + (size_t)gr * K + k0 + a_kq * 4);
            else
                a_reg[p] = make_float4(0.f, 0.f, 0.f, 0.f);
        }
        if (tid < 128) {
            b_reg[0] = *(const float4*)(B + (size_t)(k0 + 2 * b_kp)     * N + col0 + b_cq);
            b_reg[1] = *(const float4*)(B + (size_t)(k0 + 2 * b_kp + 1) * N + col0 + b_cq);
        }
    };

    auto sts_tile = [&](int s) {
        #pragma unroll
        for (int p = 0; p < 2; p++) {
            int m = a_m0 + p * 64;
            float4 v = a_reg[p];
            if (RELU_A) {
                v.x = fmaxf(v.x, 0.f); v.y = fmaxf(v.y, 0.f);
                v.z = fmaxf(v.z, 0.f); v.w = fmaxf(v.w, 0.f);
            }
            unsigned h0, l0, h1, l1;
            split_bf16x2(v.x, v.y, h0, l0);
            split_bf16x2(v.z, v.w, h1, l1);
            int off = m * AP + a_kq * 2;
            *(uint2*)&As_hi[s][off] = make_uint2(h0, h1);
            *(uint2*)&As_lo[s][off] = make_uint2(l0, l1);
        }
        if (tid < 128) {
            unsigned h[4], l[4];
            split_bf16x2(b_reg[0].x, b_reg[1].x, h[0], l[0]);
            split_bf16x2(b_reg[0].y, b_reg[1].y, h[1], l[1]);
            split_bf16x2(b_reg[0].z, b_reg[1].z, h[2], l[2]);
            split_bf16x2(b_reg[0].w, b_reg[1].w, h[3], l[3]);
            int off = b_kp * BP + b_cq;
            *(uint4*)&Bs_hi[s][off] = make_uint4(h[0], h[1], h[2], h[3]);
            *(uint4*)&Bs_lo[s][off] = make_uint4(l[0], l[1], l[2], l[3]);
        }
    };

    auto mma_pass = [&](const unsigned* As_p, const unsigned* Bs_p) {
        unsigned b[4][2];
        #pragma unroll
        for (int nt = 0; nt < 4; nt++) {
            int cb = warp_n * 32 + nt * 8 + g;
            b[nt][0] = Bs_p[tig * BP + cb];
            b[nt][1] = Bs_p[(tig + 4) * BP + cb];
        }
        #pragma unroll
        for (int mt = 0; mt < 2; mt++) {
            int rb = warp_m * 32 + mt * 16 + g;
            unsigned a[4];
            a[0] = As_p[rb * AP + tig];
            a[1] = As_p[(rb + 8) * AP + tig];
            a[2] = As_p[rb * AP + tig + 4];
            a[3] = As_p[(rb + 8) * AP + tig + 4];
            #pragma unroll
            for (int nt = 0; nt < 4; nt++)
                mma_bf16(acc[mt][nt], a, b[nt]);
        }
    };

    auto compute = [&](int s) {
        mma_pass(As_lo[s], Bs_hi[s]);
        mma_pass(As_hi[s], Bs_lo[s]);
        mma_pass(As_hi[s], Bs_hi[s]);
    };

    const int T = K / BK;
    ldg_tile(0);
    for (int t = 0; t < T; t++) {
        sts_tile(t & 1);
        __syncthreads();
        if (t + 1 < T) ldg_tile((t + 1) * BK);
        compute(t & 1);
    }

    #pragma unroll
    for (int mt = 0; mt < 2; mt++) {
        int r_lo = row0 + warp_m * 32 + mt * 16 + g;
        int r_hi = r_lo + 8;
        #pragma unroll
        for (int nt = 0; nt < 4; nt++) {
            int c = col0 + warp_n * 32 + nt * 8 + 2 * tig;
            if (r_lo < M)
                *(float2*)(C + (size_t)r_lo * N + c) =
                    make_float2(acc[mt][nt][0], acc[mt][nt][1]);
            if (r_hi < M)
                *(float2*)(C + (size_t)r_hi * N + c) =
                    make_float2(acc[mt][nt][2], acc[mt][nt][3]);
        }
    }
}

// ---------------------------------------------------------------------------
// Launch
// ---------------------------------------------------------------------------
extern "C" void kernel_launch(void* const* d_in, const int* in_sizes, int n_in,
                              void* d_out, int out_size) {
    const float* X    = (const float*)d_in[0];
    const int*   esrc = (const int*)  d_in[1];
    const int*   edst = (const int*)  d_in[2];
    const float* ew   = (const float*)d_in[3];
    const float* W1   = (const float*)d_in[4];
    const float* W2   = (const float*)d_in[5];
    float* out = (float*)d_out;

    float *H0, *H1, *H2;
    cudaGetSymbolAddress((void**)&H0, g_H0);
    cudaGetSymbolAddress((void**)&H1, g_H1);
    cudaGetSymbolAddress((void**)&H2, g_H2);

    const int T = 256;
    const int MB = (N_NODES + 127) / 128;
    const int node_blocks = (N_NODES + T - 1) / T;
    const int edge_blocks = (N_EDGES + T - 1) / T;
    const int spmm_blocks = (N_NODES * 32 + T - 1) / T;   // warp per node

    // ---- CSR build (graph shared by both layers)
    zero_deg_kernel<<<node_blocks, T>>>();
    hist_kernel<<<edge_blocks, T>>>(edst);
    scan_blocks_kernel<<<SCAN_BLOCKS, 1024>>>();
    add_off_kernel<<<node_blocks, T>>>();
    fill_kernel<<<edge_blocks, T>>>(esrc, edst, ew);

    // ---- layer 1
    gemm_tc_kernel<false><<<dim3(F_HID / 64, MB), T>>>(X, W1, H0,
                                                       N_NODES, F_HID, F_IN);
    spmm_csr_kernel<F_HID><<<spmm_blocks, T>>>(H0, H1);

    // ---- layer 2
    gemm_tc_kernel<true><<<dim3(F_OUT / 64, MB), T>>>(H1, W2, H2,
                                                      N_NODES, F_OUT, F_HID);
    spmm_csr_kernel<F_OUT><<<spmm_blocks, T>>>(H2, out);
}

// round 13
// speedup vs baseline: 1.1012x; 1.1012x over previous
#include <cuda_runtime.h>
#include <cuda_bf16.h>

#define N_NODES 50000
#define N_EDGES 800000
#define F_IN    512
#define F_HID   256
#define F_OUT   128

#define SCAN_BLOCKS 64           // 64 * 1024 >= N_NODES

// Scratch
__device__ float    g_H0[(size_t)N_NODES * F_HID];
__device__ unsigned g_H1p_hi[(size_t)N_NODES * (F_HID / 2)];  // packed bf16 pairs
__device__ unsigned g_H1p_lo[(size_t)N_NODES * (F_HID / 2)];
__device__ float    g_H2[(size_t)N_NODES * F_OUT];
__device__ int      g_deg[N_NODES];
__device__ int      g_part[N_NODES];
__device__ int      g_bsum[SCAN_BLOCKS];
__device__ int      g_offsets[N_NODES + 1];
__device__ int      g_cursor[N_NODES];
__device__ int      g_ssrc[N_EDGES];
__device__ float    g_sw[N_EDGES];
// Pre-packed weights: [K/2][N] u32, element = (bf16(W[2kp+1][n])<<16)|bf16(W[2kp][n])
__device__ unsigned g_W1p_hi[(F_IN / 2) * F_HID];
__device__ unsigned g_W1p_lo[(F_IN / 2) * F_HID];
__device__ unsigned g_W2p_hi[(F_HID / 2) * F_OUT];
__device__ unsigned g_W2p_lo[(F_HID / 2) * F_OUT];

// ---------------------------------------------------------------------------
// helpers
// ---------------------------------------------------------------------------
__device__ __forceinline__ void split_bf16x2(float f0, float f1,
                                             unsigned& hi, unsigned& lo) {
    asm("cvt.rn.bf16x2.f32 %0, %1, %2;" : "=r"(hi) : "f"(f1), "f"(f0));
    float fh0 = __uint_as_float(hi << 16);
    float fh1 = __uint_as_float(hi & 0xFFFF0000u);
    asm("cvt.rn.bf16x2.f32 %0, %1, %2;" : "=r"(lo)
        : "f"(f1 - fh1), "f"(f0 - fh0));
}

__device__ __forceinline__ void mma_bf16(float c[4], const unsigned a[4],
                                         const unsigned b[2]) {
    asm volatile(
        "mma.sync.aligned.m16n8k16.row.col.f32.bf16.bf16.f32 "
        "{%0,%1,%2,%3}, {%4,%5,%6,%7}, {%8,%9}, {%0,%1,%2,%3};"
        : "+f"(c[0]), "+f"(c[1]), "+f"(c[2]), "+f"(c[3])
        : "r"(a[0]), "r"(a[1]), "r"(a[2]), "r"(a[3]), "r"(b[0]), "r"(b[1]));
}

__device__ __forceinline__ unsigned smem_u32p(const void* p) {
    return (unsigned)__cvta_generic_to_shared(p);
}

__device__ __forceinline__ void cp_async16(unsigned dst, const void* src, int src_bytes) {
    asm volatile("cp.async.ca.shared.global [%0], [%1], 16, %2;"
                 :: "r"(dst), "l"(src), "r"(src_bytes));
}
#define CP_COMMIT() asm volatile("cp.async.commit_group;")
#define CP_WAIT_0() asm volatile("cp.async.wait_group 0;")

// ---------------------------------------------------------------------------
// Weight split+pack: W[K][N] fp32 -> Ph/Pl[K/2][N] u32 (k-pair packed bf16)
// ---------------------------------------------------------------------------
__global__ void wsplit_pack(const float* __restrict__ W,
                            unsigned* __restrict__ Ph,
                            unsigned* __restrict__ Pl, int K, int N) {
    int idx = blockIdx.x * 256 + threadIdx.x;
    if (idx >= (K / 2) * N) return;
    int kp = idx / N, n = idx - kp * N;
    float f0 = W[(size_t)(2 * kp) * N + n];
    float f1 = W[(size_t)(2 * kp + 1) * N + n];
    unsigned hi, lo;
    split_bf16x2(f0, f1, hi, lo);
    Ph[idx] = hi;
    Pl[idx] = lo;
}

// ---------------------------------------------------------------------------
// CSR build kernels
// ---------------------------------------------------------------------------
__global__ void zero_deg_kernel() {
    int i = blockIdx.x * blockDim.x + threadIdx.x;
    if (i < N_NODES) g_deg[i] = 0;
}

__global__ void hist_kernel(const int* __restrict__ dst) {
    int e = blockIdx.x * blockDim.x + threadIdx.x;
    if (e < N_EDGES) atomicAdd(&g_deg[dst[e]], 1);
}

__global__ __launch_bounds__(1024)
void scan_blocks_kernel() {
    __shared__ int sm[1024];
    int tid = threadIdx.x;
    int i = blockIdx.x * 1024 + tid;
    int v = (i < N_NODES) ? g_deg[i] : 0;
    sm[tid] = v;
    __syncthreads();
    #pragma unroll
    for (int d = 1; d < 1024; d <<= 1) {
        int t = (tid >= d) ? sm[tid - d] : 0;
        __syncthreads();
        sm[tid] += t;
        __syncthreads();
    }
    if (i < N_NODES) g_part[i] = sm[tid] - v;
    if (tid == 1023) g_bsum[blockIdx.x] = sm[1023];
}

__global__ void add_off_kernel() {
    __shared__ int s_pref;
    int seg = blockIdx.x >> 2;       // 256-thread block lies in one 1024-seg
    if (threadIdx.x == 0) {
        int p = 0;
        for (int j = 0; j < seg; j++) p += g_bsum[j];
        s_pref = p;
    }
    __syncthreads();
    int i = blockIdx.x * 256 + threadIdx.x;
    if (i < N_NODES) {
        int off = g_part[i] + s_pref;
        g_offsets[i] = off;
        g_cursor[i]  = off;
    }
    if (i == 0) g_offsets[N_NODES] = N_EDGES;
}

__global__ void fill_kernel(const int* __restrict__ src,
                            const int* __restrict__ dst,
                            const float* __restrict__ w) {
    int e = blockIdx.x * blockDim.x + threadIdx.x;
    if (e >= N_EDGES) return;
    int d = dst[e];
    int pos = atomicAdd(&g_cursor[d], 1);
    g_ssrc[pos] = src[e];
    g_sw[pos]   = w[e];
}

// ---------------------------------------------------------------------------
// SpMM layer 1: y = spmm(H0); output relu+split+packed bf16 (A-format for GEMM2)
// ---------------------------------------------------------------------------
__global__ __launch_bounds__(256)
void spmm_pack_kernel(const float* __restrict__ x) {
    int node = (blockIdx.x * 256 + threadIdx.x) >> 5;
    if (node >= N_NODES) return;
    int lane = threadIdx.x & 31;

    int beg = g_offsets[node];
    int end = g_offsets[node + 1];

    float4 acc0 = make_float4(0.f, 0.f, 0.f, 0.f);
    float4 acc1 = make_float4(0.f, 0.f, 0.f, 0.f);

    for (int j = beg; j < end; j++) {
        int s    = __ldg(&g_ssrc[j]);
        float wv = __ldg(&g_sw[j]);
        const float4* xr = (const float4*)(x + (size_t)s * F_HID);
        float4 v0 = __ldg(&xr[lane]);
        acc0.x = fmaf(wv, v0.x, acc0.x);
        acc0.y = fmaf(wv, v0.y, acc0.y);
        acc0.z = fmaf(wv, v0.z, acc0.z);
        acc0.w = fmaf(wv, v0.w, acc0.w);
        float4 v1 = __ldg(&xr[lane + 32]);
        acc1.x = fmaf(wv, v1.x, acc1.x);
        acc1.y = fmaf(wv, v1.y, acc1.y);
        acc1.z = fmaf(wv, v1.z, acc1.z);
        acc1.w = fmaf(wv, v1.w, acc1.w);
    }

    // relu + split + pack: acc0 -> kpairs 2*lane, 2*lane+1; acc1 -> +64
    acc0.x = fmaxf(acc0.x, 0.f); acc0.y = fmaxf(acc0.y, 0.f);
    acc0.z = fmaxf(acc0.z, 0.f); acc0.w = fmaxf(acc0.w, 0.f);
    acc1.x = fmaxf(acc1.x, 0.f); acc1.y = fmaxf(acc1.y, 0.f);
    acc1.z = fmaxf(acc1.z, 0.f); acc1.w = fmaxf(acc1.w, 0.f);

    unsigned h0, l0, h1, l1;
    size_t base = (size_t)node * (F_HID / 2);
    split_bf16x2(acc0.x, acc0.y, h0, l0);
    split_bf16x2(acc0.z, acc0.w, h1, l1);
    *(uint2*)&g_H1p_hi[base + 2 * lane] = make_uint2(h0, h1);
    *(uint2*)&g_H1p_lo[base + 2 * lane] = make_uint2(l0, l1);
    split_bf16x2(acc1.x, acc1.y, h0, l0);
    split_bf16x2(acc1.z, acc1.w, h1, l1);
    *(uint2*)&g_H1p_hi[base + 64 + 2 * lane] = make_uint2(h0, h1);
    *(uint2*)&g_H1p_lo[base + 64 + 2 * lane] = make_uint2(l0, l1);
}

// ---------------------------------------------------------------------------
// SpMM layer 2: out = spmm(H2), fp32 out
// ---------------------------------------------------------------------------
__global__ __launch_bounds__(256)
void spmm_csr_kernel(const float* __restrict__ x, float* __restrict__ y) {
    int node = (blockIdx.x * 256 + threadIdx.x) >> 5;
    if (node >= N_NODES) return;
    int lane = threadIdx.x & 31;

    int beg = g_offsets[node];
    int end = g_offsets[node + 1];

    float4 acc0 = make_float4(0.f, 0.f, 0.f, 0.f);
    for (int j = beg; j < end; j++) {
        int s    = __ldg(&g_ssrc[j]);
        float wv = __ldg(&g_sw[j]);
        float4 v0 = __ldg(&((const float4*)(x + (size_t)s * F_OUT))[lane]);
        acc0.x = fmaf(wv, v0.x, acc0.x);
        acc0.y = fmaf(wv, v0.y, acc0.y);
        acc0.z = fmaf(wv, v0.z, acc0.z);
        acc0.w = fmaf(wv, v0.w, acc0.w);
    }
    ((float4*)(y + (size_t)node * F_OUT))[lane] = acc0;
}

// ===========================================================================
// GEMM common: block 128x128, BK=16, 8 warps (2x4), warp tile 64x32.
// Smem u32 fragment format: As[m][kp] pitch 12, Bs[kp][n] pitch 136.
// ===========================================================================
#define AP 12
#define BP 136

struct GemmSmem {
    unsigned As_hi[2][128 * AP];
    unsigned As_lo[2][128 * AP];
    unsigned Bs_hi[2][8 * BP];
    unsigned Bs_lo[2][8 * BP];
};

__device__ __forceinline__ void mma_pass(float acc[4][4][4],
                                         const unsigned* As_p,
                                         const unsigned* Bs_p,
                                         int warp_m, int warp_n,
                                         int g, int tig) {
    unsigned b[4][2];
    #pragma unroll
    for (int nt = 0; nt < 4; nt++) {
        int cb = warp_n * 32 + nt * 8 + g;
        b[nt][0] = Bs_p[tig * BP + cb];
        b[nt][1] = Bs_p[(tig + 4) * BP + cb];
    }
    #pragma unroll
    for (int mt = 0; mt < 4; mt++) {
        int rb = warp_m * 64 + mt * 16 + g;
        unsigned a[4];
        a[0] = As_p[rb * AP + tig];
        a[1] = As_p[(rb + 8) * AP + tig];
        a[2] = As_p[rb * AP + tig + 4];
        a[3] = As_p[(rb + 8) * AP + tig + 4];
        #pragma unroll
        for (int nt = 0; nt < 4; nt++)
            mma_bf16(acc[mt][nt], a, b[nt]);
    }
}

__device__ __forceinline__ void gemm_epilogue(float acc[4][4][4],
                                              float* __restrict__ C,
                                              int row0, int col0, int M, int N,
                                              int warp_m, int warp_n,
                                              int g, int tig) {
    #pragma unroll
    for (int mt = 0; mt < 4; mt++) {
        int r_lo = row0 + warp_m * 64 + mt * 16 + g;
        int r_hi = r_lo + 8;
        #pragma unroll
        for (int nt = 0; nt < 4; nt++) {
            int c = col0 + warp_n * 32 + nt * 8 + 2 * tig;
            if (r_lo < M)
                *(float2*)(C + (size_t)r_lo * N + c) =
                    make_float2(acc[mt][nt][0], acc[mt][nt][1]);
            if (r_hi < M)
                *(float2*)(C + (size_t)r_hi * N + c) =
                    make_float2(acc[mt][nt][2], acc[mt][nt][3]);
        }
    }
}

// ---------------------------------------------------------------------------
// GEMM1: C[M,N] = A[M,K] (fp32, in-loop split) @ Wp^  (pre-packed B, cp.async)
// ---------------------------------------------------------------------------
__global__ __launch_bounds__(256, 2)
void gemm1_kernel(const float* __restrict__ A,
                  const unsigned* __restrict__ Bph,
                  const unsigned* __restrict__ Bpl,
                  float* __restrict__ C, int M, int N, int K) {
    __shared__ __align__(16) GemmSmem sm;

    const int tid  = threadIdx.x;
    const int lane = tid & 31;
    const int warp = tid >> 5;
    const int g    = lane >> 2;
    const int tig  = lane & 3;
    const int warp_m = warp & 1;
    const int warp_n = warp >> 1;

    const int row0 = blockIdx.y * 128;
    const int col0 = blockIdx.x * 128;

    const int a_m0 = tid >> 2;          // 0..63 (+64)
    const int a_kq = tid & 3;
    const int b_r  = tid >> 5;          // 0..7  (B kpair row)
    const int b_s  = (tid & 31) * 4;    // u32 seg within row

    float acc[4][4][4];
    #pragma unroll
    for (int i = 0; i < 4; i++)
        #pragma unroll
        for (int j = 0; j < 4; j++)
            #pragma unroll
            for (int l = 0; l < 4; l++) acc[i][j][l] = 0.f;

    float4 a_reg[2];

    auto ldg_a = [&](int k0) {
        #pragma unroll
        for (int p = 0; p < 2; p++) {
            int gr = row0 + a_m0 + p * 64;
            a_reg[p] = (gr < M)
                ? *(const float4*)(A + (size_t)gr * K + k0 + a_kq * 4)
                : make_float4(0.f, 0.f, 0.f, 0.f);
        }
    };

    auto sts_a = [&](int s) {
        #pragma unroll
        for (int p = 0; p < 2; p++) {
            int m = a_m0 + p * 64;
            unsigned h0, l0, h1, l1;
            split_bf16x2(a_reg[p].x, a_reg[p].y, h0, l0);
            split_bf16x2(a_reg[p].z, a_reg[p].w, h1, l1);
            int off = m * AP + a_kq * 2;
            *(uint2*)&sm.As_hi[s][off] = make_uint2(h0, h1);
            *(uint2*)&sm.As_lo[s][off] = make_uint2(l0, l1);
        }
    };

    auto cp_b = [&](int s, int t) {
        const unsigned* sh = Bph + (size_t)(t * 8 + b_r) * N + col0 + b_s;
        const unsigned* sl = Bpl + (size_t)(t * 8 + b_r) * N + col0 + b_s;
        cp_async16(smem_u32p(&sm.Bs_hi[s][b_r * BP + b_s]), sh, 16);
        cp_async16(smem_u32p(&sm.Bs_lo[s][b_r * BP + b_s]), sl, 16);
    };

    const int T = K / 16;
    ldg_a(0);
    cp_b(0, 0);
    CP_COMMIT();
    for (int t = 0; t < T; t++) {
        int s = t & 1;
        sts_a(s);
        if (t + 1 < T) ldg_a((t + 1) * 16);
        CP_WAIT_0();
        __syncthreads();
        if (t + 1 < T) { cp_b((t + 1) & 1, t + 1); CP_COMMIT(); }
        mma_pass(acc, sm.As_lo[s], sm.Bs_hi[s], warp_m, warp_n, g, tig);
        mma_pass(acc, sm.As_hi[s], sm.Bs_lo[s], warp_m, warp_n, g, tig);
        mma_pass(acc, sm.As_hi[s], sm.Bs_hi[s], warp_m, warp_n, g, tig);
    }
    gemm_epilogue(acc, C, row0, col0, M, N, warp_m, warp_n, g, tig);
}

// ---------------------------------------------------------------------------
// GEMM2: C[M,N] = Ap (pre-packed, cp.async) @ Wp (pre-packed, cp.async)
// ---------------------------------------------------------------------------
__global__ __launch_bounds__(256, 2)
void gemm2_kernel(const unsigned* __restrict__ Aph,
                  const unsigned* __restrict__ Apl,
                  const unsigned* __restrict__ Bph,
                  const unsigned* __restrict__ Bpl,
                  float* __restrict__ C, int M, int N, int K) {
    __shared__ __align__(16) GemmSmem sm;

    const int tid  = threadIdx.x;
    const int lane = tid & 31;
    const int warp = tid >> 5;
    const int g    = lane >> 2;
    const int tig  = lane & 3;
    const int warp_m = warp & 1;
    const int warp_n = warp >> 1;

    const int row0 = blockIdx.y * 128;
    const int col0 = blockIdx.x * 128;
    const int KP = K / 2;               // packed row length (u32)

    const int a_m = tid >> 1;           // 0..127
    const int a_h = (tid & 1) * 4;      // u32 half-offset within 8-u32 row
    const int b_r = tid >> 5;
    const int b_s = (tid & 31) * 4;

    float acc[4][4][4];
    #pragma unroll
    for (int i = 0; i < 4; i++)
        #pragma unroll
        for (int j = 0; j < 4; j++)
            #pragma unroll
            for (int l = 0; l < 4; l++) acc[i][j][l] = 0.f;

    auto cp_tile = [&](int s, int t) {
        // A: 128 rows x 8 u32; each thread: one 16B chunk of hi and lo
        int gr = row0 + a_m;
        int ok = (gr < M) ? 16 : 0;
        const unsigned* sh = Aph + (size_t)(gr < M ? gr : 0) * KP + t * 8 + a_h;
        const unsigned* sl = Apl + (size_t)(gr < M ? gr : 0) * KP + t * 8 + a_h;
        cp_async16(smem_u32p(&sm.As_hi[s][a_m * AP + a_h]), sh, ok);
        cp_async16(smem_u32p(&sm.As_lo[s][a_m * AP + a_h]), sl, ok);
        // B: 8 rows x 128 u32
        const unsigned* bh = Bph + (size_t)(t * 8 + b_r) * N + col0 + b_s;
        const unsigned* bl = Bpl + (size_t)(t * 8 + b_r) * N + col0 + b_s;
        cp_async16(smem_u32p(&sm.Bs_hi[s][b_r * BP + b_s]), bh, 16);
        cp_async16(smem_u32p(&sm.Bs_lo[s][b_r * BP + b_s]), bl, 16);
    };

    const int T = K / 16;
    cp_tile(0, 0);
    CP_COMMIT();
    for (int t = 0; t < T; t++) {
        int s = t & 1;
        CP_WAIT_0();
        __syncthreads();
        if (t + 1 < T) { cp_tile((t + 1) & 1, t + 1); CP_COMMIT(); }
        mma_pass(acc, sm.As_lo[s], sm.Bs_hi[s], warp_m, warp_n, g, tig);
        mma_pass(acc, sm.As_hi[s], sm.Bs_lo[s], warp_m, warp_n, g, tig);
        mma_pass(acc, sm.As_hi[s], sm.Bs_hi[s], warp_m, warp_n, g, tig);
    }
    gemm_epilogue(acc, C, row0, col0, M, N, warp_m, warp_n, g, tig);
}

// ---------------------------------------------------------------------------
// Launch
// ---------------------------------------------------------------------------
extern "C" void kernel_launch(void* const* d_in, const int* in_sizes, int n_in,
                              void* d_out, int out_size) {
    const float* X    = (const float*)d_in[0];
    const int*   esrc = (const int*)  d_in[1];
    const int*   edst = (const int*)  d_in[2];
    const float* ew   = (const float*)d_in[3];
    const float* W1   = (const float*)d_in[4];
    const float* W2   = (const float*)d_in[5];
    float* out = (float*)d_out;

    float *H0, *H2;
    unsigned *H1ph, *H1pl, *W1ph, *W1pl, *W2ph, *W2pl;
    cudaGetSymbolAddress((void**)&H0,   g_H0);
    cudaGetSymbolAddress((void**)&H2,   g_H2);
    cudaGetSymbolAddress((void**)&H1ph, g_H1p_hi);
    cudaGetSymbolAddress((void**)&H1pl, g_H1p_lo);
    cudaGetSymbolAddress((void**)&W1ph, g_W1p_hi);
    cudaGetSymbolAddress((void**)&W1pl, g_W1p_lo);
    cudaGetSymbolAddress((void**)&W2ph, g_W2p_hi);
    cudaGetSymbolAddress((void**)&W2pl, g_W2p_lo);

    const int T = 256;
    const int MB = (N_NODES + 127) / 128;
    const int node_blocks = (N_NODES + T - 1) / T;
    const int edge_blocks = (N_EDGES + T - 1) / T;
    const int spmm_blocks = (N_NODES * 32 + T - 1) / T;

    // ---- weight pre-split/pack
    wsplit_pack<<<((F_IN / 2) * F_HID + T - 1) / T, T>>>(W1, W1ph, W1pl, F_IN, F_HID);
    wsplit_pack<<<((F_HID / 2) * F_OUT + T - 1) / T, T>>>(W2, W2ph, W2pl, F_HID, F_OUT);

    // ---- CSR build
    zero_deg_kernel<<<node_blocks, T>>>();
    hist_kernel<<<edge_blocks, T>>>(edst);
    scan_blocks_kernel<<<SCAN_BLOCKS, 1024>>>();
    add_off_kernel<<<node_blocks, T>>>();
    fill_kernel<<<edge_blocks, T>>>(esrc, edst, ew);

    // ---- layer 1: H0 = X @ W1 ; H1p = relu(spmm(H0)) packed
    gemm1_kernel<<<dim3(F_HID / 128, MB), T>>>(X, W1ph, W1pl, H0,
                                               N_NODES, F_HID, F_IN);
    spmm_pack_kernel<<<spmm_blocks, T>>>(H0);

    // ---- layer 2: H2 = H1p @ W2 ; out = spmm(H2)
    gemm2_kernel<<<dim3(F_OUT / 128, MB), T>>>(H1ph, H1pl, W2ph, W2pl, H2,
                                               N_NODES, F_OUT, F_HID);
    spmm_csr_kernel<<<spmm_blocks, T>>>(H2, out);
}

// round 14
// speedup vs baseline: 1.4486x; 1.3155x over previous
#include <cuda_runtime.h>
#include <cuda_fp16.h>

#define N_NODES 50000
#define N_EDGES 800000
#define F_IN    512
#define F_HID   256
#define F_OUT   128

#define SCAN_BLOCKS 64           // 64 * 1024 >= N_NODES

// Scratch
__device__ float    g_H0[(size_t)N_NODES * F_HID];
__device__ unsigned g_H1p[(size_t)N_NODES * (F_HID / 2)];   // packed fp16 k-pairs
__device__ float    g_H2[(size_t)N_NODES * F_OUT];
__device__ int      g_deg[N_NODES];
__device__ int      g_part[N_NODES];
__device__ int      g_bsum[SCAN_BLOCKS];
__device__ int      g_offsets[N_NODES + 1];
__device__ int      g_cursor[N_NODES];
__device__ int      g_ssrc[N_EDGES];
__device__ float    g_sw[N_EDGES];
// Pre-packed weights: [K/2][N] u32 = (fp16(W[2kp+1][n])<<16) | fp16(W[2kp][n])
__device__ unsigned g_W1p[(F_IN / 2) * F_HID];
__device__ unsigned g_W2p[(F_HID / 2) * F_OUT];

// ---------------------------------------------------------------------------
// helpers
// ---------------------------------------------------------------------------
__device__ __forceinline__ unsigned cvt_f16x2(float f0, float f1) {
    unsigned p;   // f0 -> low half (even k), f1 -> high half (odd k)
    asm("cvt.rn.f16x2.f32 %0, %1, %2;" : "=r"(p) : "f"(f1), "f"(f0));
    return p;
}

__device__ __forceinline__ void mma_f16(float c[4], const unsigned a[4],
                                        const unsigned b[2]) {
    asm volatile(
        "mma.sync.aligned.m16n8k16.row.col.f32.f16.f16.f32 "
        "{%0,%1,%2,%3}, {%4,%5,%6,%7}, {%8,%9}, {%0,%1,%2,%3};"
        : "+f"(c[0]), "+f"(c[1]), "+f"(c[2]), "+f"(c[3])
        : "r"(a[0]), "r"(a[1]), "r"(a[2]), "r"(a[3]), "r"(b[0]), "r"(b[1]));
}

__device__ __forceinline__ unsigned smem_u32p(const void* p) {
    return (unsigned)__cvta_generic_to_shared(p);
}

__device__ __forceinline__ void cp_async16(unsigned dst, const void* src, int src_bytes) {
    asm volatile("cp.async.ca.shared.global [%0], [%1], 16, %2;"
                 :: "r"(dst), "l"(src), "r"(src_bytes));
}
#define CP_COMMIT() asm volatile("cp.async.commit_group;")
#define CP_WAIT_0() asm volatile("cp.async.wait_group 0;")

// ---------------------------------------------------------------------------
// Weight pack: W[K][N] fp32 -> Wp[K/2][N] u32 (fp16 k-pair packed)
// ---------------------------------------------------------------------------
__global__ void wpack_kernel(const float* __restrict__ W,
                             unsigned* __restrict__ Wp, int K, int N) {
    int idx = blockIdx.x * 256 + threadIdx.x;
    if (idx >= (K / 2) * N) return;
    int kp = idx / N, n = idx - kp * N;
    float f0 = W[(size_t)(2 * kp) * N + n];
    float f1 = W[(size_t)(2 * kp + 1) * N + n];
    Wp[idx] = cvt_f16x2(f0, f1);
}

// ---------------------------------------------------------------------------
// CSR build kernels
// ---------------------------------------------------------------------------
__global__ void zero_deg_kernel() {
    int i = blockIdx.x * blockDim.x + threadIdx.x;
    if (i < N_NODES) g_deg[i] = 0;
}

__global__ void hist_kernel(const int* __restrict__ dst) {
    int e = blockIdx.x * blockDim.x + threadIdx.x;
    if (e < N_EDGES) atomicAdd(&g_deg[dst[e]], 1);
}

__global__ __launch_bounds__(1024)
void scan_blocks_kernel() {
    __shared__ int sm[1024];
    int tid = threadIdx.x;
    int i = blockIdx.x * 1024 + tid;
    int v = (i < N_NODES) ? g_deg[i] : 0;
    sm[tid] = v;
    __syncthreads();
    #pragma unroll
    for (int d = 1; d < 1024; d <<= 1) {
        int t = (tid >= d) ? sm[tid - d] : 0;
        __syncthreads();
        sm[tid] += t;
        __syncthreads();
    }
    if (i < N_NODES) g_part[i] = sm[tid] - v;
    if (tid == 1023) g_bsum[blockIdx.x] = sm[1023];
}

__global__ void add_off_kernel() {
    __shared__ int s_pref;
    int seg = blockIdx.x >> 2;       // 256-thread block lies in one 1024-seg
    if (threadIdx.x == 0) {
        int p = 0;
        for (int j = 0; j < seg; j++) p += g_bsum[j];
        s_pref = p;
    }
    __syncthreads();
    int i = blockIdx.x * 256 + threadIdx.x;
    if (i < N_NODES) {
        int off = g_part[i] + s_pref;
        g_offsets[i] = off;
        g_cursor[i]  = off;
    }
    if (i == 0) g_offsets[N_NODES] = N_EDGES;
}

__global__ void fill_kernel(const int* __restrict__ src,
                            const int* __restrict__ dst,
                            const float* __restrict__ w) {
    int e = blockIdx.x * blockDim.x + threadIdx.x;
    if (e >= N_EDGES) return;
    int d = dst[e];
    int pos = atomicAdd(&g_cursor[d], 1);
    g_ssrc[pos] = src[e];
    g_sw[pos]   = w[e];
}

// ---------------------------------------------------------------------------
// SpMM layer 1: H1p = pack_f16(relu(spmm(H0)))
// ---------------------------------------------------------------------------
__global__ __launch_bounds__(256)
void spmm_pack_kernel(const float* __restrict__ x) {
    int node = (blockIdx.x * 256 + threadIdx.x) >> 5;
    if (node >= N_NODES) return;
    int lane = threadIdx.x & 31;

    int beg = g_offsets[node];
    int end = g_offsets[node + 1];

    float4 acc0 = make_float4(0.f, 0.f, 0.f, 0.f);
    float4 acc1 = make_float4(0.f, 0.f, 0.f, 0.f);

    for (int j = beg; j < end; j++) {
        int s    = __ldg(&g_ssrc[j]);
        float wv = __ldg(&g_sw[j]);
        const float4* xr = (const float4*)(x + (size_t)s * F_HID);
        float4 v0 = __ldg(&xr[lane]);
        acc0.x = fmaf(wv, v0.x, acc0.x);
        acc0.y = fmaf(wv, v0.y, acc0.y);
        acc0.z = fmaf(wv, v0.z, acc0.z);
        acc0.w = fmaf(wv, v0.w, acc0.w);
        float4 v1 = __ldg(&xr[lane + 32]);
        acc1.x = fmaf(wv, v1.x, acc1.x);
        acc1.y = fmaf(wv, v1.y, acc1.y);
        acc1.z = fmaf(wv, v1.z, acc1.z);
        acc1.w = fmaf(wv, v1.w, acc1.w);
    }

    acc0.x = fmaxf(acc0.x, 0.f); acc0.y = fmaxf(acc0.y, 0.f);
    acc0.z = fmaxf(acc0.z, 0.f); acc0.w = fmaxf(acc0.w, 0.f);
    acc1.x = fmaxf(acc1.x, 0.f); acc1.y = fmaxf(acc1.y, 0.f);
    acc1.z = fmaxf(acc1.z, 0.f); acc1.w = fmaxf(acc1.w, 0.f);

    size_t base = (size_t)node * (F_HID / 2);
    *(uint2*)&g_H1p[base + 2 * lane] =
        make_uint2(cvt_f16x2(acc0.x, acc0.y), cvt_f16x2(acc0.z, acc0.w));
    *(uint2*)&g_H1p[base + 64 + 2 * lane] =
        make_uint2(cvt_f16x2(acc1.x, acc1.y), cvt_f16x2(acc1.z, acc1.w));
}

// ---------------------------------------------------------------------------
// SpMM layer 2: out = spmm(H2), fp32
// ---------------------------------------------------------------------------
__global__ __launch_bounds__(256)
void spmm_csr_kernel(const float* __restrict__ x, float* __restrict__ y) {
    int node = (blockIdx.x * 256 + threadIdx.x) >> 5;
    if (node >= N_NODES) return;
    int lane = threadIdx.x & 31;

    int beg = g_offsets[node];
    int end = g_offsets[node + 1];

    float4 acc0 = make_float4(0.f, 0.f, 0.f, 0.f);
    for (int j = beg; j < end; j++) {
        int s    = __ldg(&g_ssrc[j]);
        float wv = __ldg(&g_sw[j]);
        float4 v0 = __ldg(&((const float4*)(x + (size_t)s * F_OUT))[lane]);
        acc0.x = fmaf(wv, v0.x, acc0.x);
        acc0.y = fmaf(wv, v0.y, acc0.y);
        acc0.z = fmaf(wv, v0.z, acc0.z);
        acc0.w = fmaf(wv, v0.w, acc0.w);
    }
    ((float4*)(y + (size_t)node * F_OUT))[lane] = acc0;
}

// ===========================================================================
// GEMM common: block 128x128, BK=16, 8 warps (2x4), warp tile 64x32,
// single fp16 MMA per fragment. Smem: As[m][kp] pitch 12, Bs[kp][n] pitch 136.
// ===========================================================================
#define AP 12
#define BP 136

struct GemmSmem {
    unsigned As[2][128 * AP];
    unsigned Bs[2][8 * BP];
};

__device__ __forceinline__ void mma_pass(float acc[4][4][4],
                                         const unsigned* As_p,
                                         const unsigned* Bs_p,
                                         int warp_m, int warp_n,
                                         int g, int tig) {
    unsigned b[4][2];
    #pragma unroll
    for (int nt = 0; nt < 4; nt++) {
        int cb = warp_n * 32 + nt * 8 + g;
        b[nt][0] = Bs_p[tig * BP + cb];
        b[nt][1] = Bs_p[(tig + 4) * BP + cb];
    }
    #pragma unroll
    for (int mt = 0; mt < 4; mt++) {
        int rb = warp_m * 64 + mt * 16 + g;
        unsigned a[4];
        a[0] = As_p[rb * AP + tig];
        a[1] = As_p[(rb + 8) * AP + tig];
        a[2] = As_p[rb * AP + tig + 4];
        a[3] = As_p[(rb + 8) * AP + tig + 4];
        #pragma unroll
        for (int nt = 0; nt < 4; nt++)
            mma_f16(acc[mt][nt], a, b[nt]);
    }
}

__device__ __forceinline__ void gemm_epilogue(float acc[4][4][4],
                                              float* __restrict__ C,
                                              int row0, int col0, int M, int N,
                                              int warp_m, int warp_n,
                                              int g, int tig) {
    #pragma unroll
    for (int mt = 0; mt < 4; mt++) {
        int r_lo = row0 + warp_m * 64 + mt * 16 + g;
        int r_hi = r_lo + 8;
        #pragma unroll
        for (int nt = 0; nt < 4; nt++) {
            int c = col0 + warp_n * 32 + nt * 8 + 2 * tig;
            if (r_lo < M)
                *(float2*)(C + (size_t)r_lo * N + c) =
                    make_float2(acc[mt][nt][0], acc[mt][nt][1]);
            if (r_hi < M)
                *(float2*)(C + (size_t)r_hi * N + c) =
                    make_float2(acc[mt][nt][2], acc[mt][nt][3]);
        }
    }
}

// ---------------------------------------------------------------------------
// GEMM1: C = A (fp32, cvt in-loop) @ Wp  (pre-packed fp16 B via cp.async)
// ---------------------------------------------------------------------------
__global__ __launch_bounds__(256, 2)
void gemm1_kernel(const float* __restrict__ A,
                  const unsigned* __restrict__ Bp,
                  float* __restrict__ C, int M, int N, int K) {
    __shared__ __align__(16) GemmSmem sm;

    const int tid  = threadIdx.x;
    const int lane = tid & 31;
    const int warp = tid >> 5;
    const int g    = lane >> 2;
    const int tig  = lane & 3;
    const int warp_m = warp & 1;
    const int warp_n = warp >> 1;

    const int row0 = blockIdx.y * 128;
    const int col0 = blockIdx.x * 128;

    const int a_m0 = tid >> 2;          // 0..63 (+64)
    const int a_kq = tid & 3;
    const int b_r  = tid >> 5;
    const int b_s  = (tid & 31) * 4;

    float acc[4][4][4];
    #pragma unroll
    for (int i = 0; i < 4; i++)
        #pragma unroll
        for (int j = 0; j < 4; j++)
            #pragma unroll
            for (int l = 0; l < 4; l++) acc[i][j][l] = 0.f;

    float4 a_reg[2];

    auto ldg_a = [&](int k0) {
        #pragma unroll
        for (int p = 0; p < 2; p++) {
            int gr = row0 + a_m0 + p * 64;
            a_reg[p] = (gr < M)
                ? *(const float4*)(A + (size_t)gr * K + k0 + a_kq * 4)
                : make_float4(0.f, 0.f, 0.f, 0.f);
        }
    };

    auto sts_a = [&](int s) {
        #pragma unroll
        for (int p = 0; p < 2; p++) {
            int m = a_m0 + p * 64;
            int off = m * AP + a_kq * 2;
            *(uint2*)&sm.As[s][off] =
                make_uint2(cvt_f16x2(a_reg[p].x, a_reg[p].y),
                           cvt_f16x2(a_reg[p].z, a_reg[p].w));
        }
    };

    auto cp_b = [&](int s, int t) {
        const unsigned* src = Bp + (size_t)(t * 8 + b_r) * N + col0 + b_s;
        cp_async16(smem_u32p(&sm.Bs[s][b_r * BP + b_s]), src, 16);
    };

    const int T = K / 16;
    ldg_a(0);
    cp_b(0, 0);
    CP_COMMIT();
    for (int t = 0; t < T; t++) {
        int s = t & 1;
        sts_a(s);
        if (t + 1 < T) ldg_a((t + 1) * 16);
        CP_WAIT_0();
        __syncthreads();
        if (t + 1 < T) { cp_b((t + 1) & 1, t + 1); CP_COMMIT(); }
        mma_pass(acc, sm.As[s], sm.Bs[s], warp_m, warp_n, g, tig);
        __syncthreads();
    }
    gemm_epilogue(acc, C, row0, col0, M, N, warp_m, warp_n, g, tig);
}

// ---------------------------------------------------------------------------
// GEMM2: C = Ap (pre-packed fp16, cp.async) @ Wp (pre-packed, cp.async)
// ---------------------------------------------------------------------------
__global__ __launch_bounds__(256, 2)
void gemm2_kernel(const unsigned* __restrict__ Ap,
                  const unsigned* __restrict__ Bp,
                  float* __restrict__ C, int M, int N, int K) {
    __shared__ __align__(16) GemmSmem sm;

    const int tid  = threadIdx.x;
    const int lane = tid & 31;
    const int warp = tid >> 5;
    const int g    = lane >> 2;
    const int tig  = lane & 3;
    const int warp_m = warp & 1;
    const int warp_n = warp >> 1;

    const int row0 = blockIdx.y * 128;
    const int col0 = blockIdx.x * 128;
    const int KP = K / 2;

    const int a_m = tid >> 1;           // 0..127
    const int a_h = (tid & 1) * 4;
    const int b_r = tid >> 5;
    const int b_s = (tid & 31) * 4;

    float acc[4][4][4];
    #pragma unroll
    for (int i = 0; i < 4; i++)
        #pragma unroll
        for (int j = 0; j < 4; j++)
            #pragma unroll
            for (int l = 0; l < 4; l++) acc[i][j][l] = 0.f;

    auto cp_tile = [&](int s, int t) {
        int gr = row0 + a_m;
        int ok = (gr < M) ? 16 : 0;
        const unsigned* sa = Ap + (size_t)(gr < M ? gr : 0) * KP + t * 8 + a_h;
        cp_async16(smem_u32p(&sm.As[s][a_m * AP + a_h]), sa, ok);
        const unsigned* sb = Bp + (size_t)(t * 8 + b_r) * N + col0 + b_s;
        cp_async16(smem_u32p(&sm.Bs[s][b_r * BP + b_s]), sb, 16);
    };

    const int T = K / 16;
    cp_tile(0, 0);
    CP_COMMIT();
    for (int t = 0; t < T; t++) {
        int s = t & 1;
        CP_WAIT_0();
        __syncthreads();
        if (t + 1 < T) { cp_tile((t + 1) & 1, t + 1); CP_COMMIT(); }
        mma_pass(acc, sm.As[s], sm.Bs[s], warp_m, warp_n, g, tig);
        __syncthreads();
    }
    gemm_epilogue(acc, C, row0, col0, M, N, warp_m, warp_n, g, tig);
}

// ---------------------------------------------------------------------------
// Launch
// ---------------------------------------------------------------------------
extern "C" void kernel_launch(void* const* d_in, const int* in_sizes, int n_in,
                              void* d_out, int out_size) {
    const float* X    = (const float*)d_in[0];
    const int*   esrc = (const int*)  d_in[1];
    const int*   edst = (const int*)  d_in[2];
    const float* ew   = (const float*)d_in[3];
    const float* W1   = (const float*)d_in[4];
    const float* W2   = (const float*)d_in[5];
    float* out = (float*)d_out;

    float *H0, *H2;
    unsigned *H1p, *W1p, *W2p;
    cudaGetSymbolAddress((void**)&H0,  g_H0);
    cudaGetSymbolAddress((void**)&H2,  g_H2);
    cudaGetSymbolAddress((void**)&H1p, g_H1p);
    cudaGetSymbolAddress((void**)&W1p, g_W1p);
    cudaGetSymbolAddress((void**)&W2p, g_W2p);

    const int T = 256;
    const int MB = (N_NODES + 127) / 128;
    const int node_blocks = (N_NODES + T - 1) / T;
    const int edge_blocks = (N_EDGES + T - 1) / T;
    const int spmm_blocks = (N_NODES * 32 + T - 1) / T;

    // ---- weight pre-pack (fp16)
    wpack_kernel<<<((F_IN / 2) * F_HID + T - 1) / T, T>>>(W1, W1p, F_IN, F_HID);
    wpack_kernel<<<((F_HID / 2) * F_OUT + T - 1) / T, T>>>(W2, W2p, F_HID, F_OUT);

    // ---- CSR build
    zero_deg_kernel<<<node_blocks, T>>>();
    hist_kernel<<<edge_blocks, T>>>(edst);
    scan_blocks_kernel<<<SCAN_BLOCKS, 1024>>>();
    add_off_kernel<<<node_blocks, T>>>();
    fill_kernel<<<edge_blocks, T>>>(esrc, edst, ew);

    // ---- layer 1: H0 = X @ W1 ; H1p = pack(relu(spmm(H0)))
    gemm1_kernel<<<dim3(F_HID / 128, MB), T>>>(X, W1p, H0, N_NODES, F_HID, F_IN);
    spmm_pack_kernel<<<spmm_blocks, T>>>(H0);

    // ---- layer 2: H2 = H1p @ W2 ; out = spmm(H2)
    gemm2_kernel<<<dim3(F_OUT / 128, MB), T>>>(H1p, W2p, H2, N_NODES, F_OUT, F_HID);
    spmm_csr_kernel<<<spmm_blocks, T>>>(H2, out);
}

// round 15
// speedup vs baseline: 1.6750x; 1.1562x over previous
#include <cuda_runtime.h>
#include <cuda_fp16.h>

#define N_NODES 50000
#define N_EDGES 800000
#define F_IN    512
#define F_HID   256
#define F_OUT   128

#define SCAN_BLOCKS 64           // 64 * 1024 >= N_NODES

// Scratch (all intermediates packed fp16 k-pairs: u32 j = features 2j, 2j+1)
__device__ unsigned g_H0p[(size_t)N_NODES * (F_HID / 2)];
__device__ unsigned g_H1p[(size_t)N_NODES * (F_HID / 2)];
__device__ unsigned g_H2p[(size_t)N_NODES * (F_OUT / 2)];
__device__ int      g_deg[N_NODES];
__device__ int      g_part[N_NODES];
__device__ int      g_bsum[SCAN_BLOCKS];
__device__ int      g_offsets[N_NODES + 1];
__device__ int      g_cursor[N_NODES];
__device__ int2     g_edge[N_EDGES];          // {src, float_bits(w)} dst-sorted
// Pre-packed weights: [K/2][N] u32 = (fp16(W[2kp+1][n])<<16) | fp16(W[2kp][n])
__device__ unsigned g_W1p[(F_IN / 2) * F_HID];
__device__ unsigned g_W2p[(F_HID / 2) * F_OUT];

// ---------------------------------------------------------------------------
// helpers
// ---------------------------------------------------------------------------
__device__ __forceinline__ unsigned cvt_f16x2(float f0, float f1) {
    unsigned p;   // f0 -> low half (even k), f1 -> high half (odd k)
    asm("cvt.rn.f16x2.f32 %0, %1, %2;" : "=r"(p) : "f"(f1), "f"(f0));
    return p;
}

__device__ __forceinline__ float2 unpack_f16x2(unsigned p) {
    return __half22float2(*(__half2*)&p);
}

__device__ __forceinline__ void mma_f16(float c[4], const unsigned a[4],
                                        const unsigned b[2]) {
    asm volatile(
        "mma.sync.aligned.m16n8k16.row.col.f32.f16.f16.f32 "
        "{%0,%1,%2,%3}, {%4,%5,%6,%7}, {%8,%9}, {%0,%1,%2,%3};"
        : "+f"(c[0]), "+f"(c[1]), "+f"(c[2]), "+f"(c[3])
        : "r"(a[0]), "r"(a[1]), "r"(a[2]), "r"(a[3]), "r"(b[0]), "r"(b[1]));
}

__device__ __forceinline__ unsigned smem_u32p(const void* p) {
    return (unsigned)__cvta_generic_to_shared(p);
}

__device__ __forceinline__ void cp_async16(unsigned dst, const void* src, int src_bytes) {
    asm volatile("cp.async.ca.shared.global [%0], [%1], 16, %2;"
                 :: "r"(dst), "l"(src), "r"(src_bytes));
}
#define CP_COMMIT() asm volatile("cp.async.commit_group;")
#define CP_WAIT_0() asm volatile("cp.async.wait_group 0;")

// ---------------------------------------------------------------------------
// Weight pack: W[K][N] fp32 -> Wp[K/2][N] u32 (fp16 k-pair packed)
// ---------------------------------------------------------------------------
__global__ void wpack_kernel(const float* __restrict__ W,
                             unsigned* __restrict__ Wp, int K, int N) {
    int idx = blockIdx.x * 256 + threadIdx.x;
    if (idx >= (K / 2) * N) return;
    int kp = idx / N, n = idx - kp * N;
    Wp[idx] = cvt_f16x2(W[(size_t)(2 * kp) * N + n],
                        W[(size_t)(2 * kp + 1) * N + n]);
}

// ---------------------------------------------------------------------------
// CSR build kernels
// ---------------------------------------------------------------------------
__global__ void zero_deg_kernel() {
    int i = blockIdx.x * blockDim.x + threadIdx.x;
    if (i < N_NODES) g_deg[i] = 0;
}

__global__ void hist_kernel(const int* __restrict__ dst) {
    int e = blockIdx.x * blockDim.x + threadIdx.x;
    if (e < N_EDGES) atomicAdd(&g_deg[dst[e]], 1);
}

__global__ __launch_bounds__(1024)
void scan_blocks_kernel() {
    __shared__ int sm[1024];
    int tid = threadIdx.x;
    int i = blockIdx.x * 1024 + tid;
    int v = (i < N_NODES) ? g_deg[i] : 0;
    sm[tid] = v;
    __syncthreads();
    #pragma unroll
    for (int d = 1; d < 1024; d <<= 1) {
        int t = (tid >= d) ? sm[tid - d] : 0;
        __syncthreads();
        sm[tid] += t;
        __syncthreads();
    }
    if (i < N_NODES) g_part[i] = sm[tid] - v;
    if (tid == 1023) g_bsum[blockIdx.x] = sm[1023];
}

__global__ void add_off_kernel() {
    __shared__ int s_pref;
    int seg = blockIdx.x >> 2;       // 256-thread block lies in one 1024-seg
    if (threadIdx.x == 0) {
        int p = 0;
        for (int j = 0; j < seg; j++) p += g_bsum[j];
        s_pref = p;
    }
    __syncthreads();
    int i = blockIdx.x * 256 + threadIdx.x;
    if (i < N_NODES) {
        int off = g_part[i] + s_pref;
        g_offsets[i] = off;
        g_cursor[i]  = off;
    }
    if (i == 0) g_offsets[N_NODES] = N_EDGES;
}

__global__ void fill_kernel(const int* __restrict__ src,
                            const int* __restrict__ dst,
                            const float* __restrict__ w) {
    int e = blockIdx.x * blockDim.x + threadIdx.x;
    if (e >= N_EDGES) return;
    int pos = atomicAdd(&g_cursor[dst[e]], 1);
    g_edge[pos] = make_int2(src[e], __float_as_int(w[e]));
}

// ---------------------------------------------------------------------------
// SpMM layer 1: H1p = pack(relu(spmm(H0p)))  — fp16 gather, fp32 accumulate
// warp per node; row = F_HID/2 = 128 u32; lane covers u32 [4*lane, 4*lane+4)
// ---------------------------------------------------------------------------
__global__ __launch_bounds__(256)
void spmm1_kernel() {
    int node = (blockIdx.x * 256 + threadIdx.x) >> 5;
    if (node >= N_NODES) return;
    int lane = threadIdx.x & 31;

    int beg = g_offsets[node];
    int end = g_offsets[node + 1];

    float acc[8] = {};
    for (int j = beg; j < end; j++) {
        int2 e = __ldg(&g_edge[j]);
        float wv = __int_as_float(e.y);
        uint4 v = __ldg(&((const uint4*)(g_H0p + (size_t)e.x * (F_HID / 2)))[lane]);
        float2 f0 = unpack_f16x2(v.x), f1 = unpack_f16x2(v.y);
        float2 f2 = unpack_f16x2(v.z), f3 = unpack_f16x2(v.w);
        acc[0] = fmaf(wv, f0.x, acc[0]); acc[1] = fmaf(wv, f0.y, acc[1]);
        acc[2] = fmaf(wv, f1.x, acc[2]); acc[3] = fmaf(wv, f1.y, acc[3]);
        acc[4] = fmaf(wv, f2.x, acc[4]); acc[5] = fmaf(wv, f2.y, acc[5]);
        acc[6] = fmaf(wv, f3.x, acc[6]); acc[7] = fmaf(wv, f3.y, acc[7]);
    }
    #pragma unroll
    for (int i = 0; i < 8; i++) acc[i] = fmaxf(acc[i], 0.f);

    uint4 o;
    o.x = cvt_f16x2(acc[0], acc[1]);
    o.y = cvt_f16x2(acc[2], acc[3]);
    o.z = cvt_f16x2(acc[4], acc[5]);
    o.w = cvt_f16x2(acc[6], acc[7]);
    ((uint4*)(g_H1p + (size_t)node * (F_HID / 2)))[lane] = o;
}

// ---------------------------------------------------------------------------
// SpMM layer 2: out = spmm(H2p), fp32 out
// row = F_OUT/2 = 64 u32; lane covers u32 [2*lane, 2*lane+2)
// ---------------------------------------------------------------------------
__global__ __launch_bounds__(256)
void spmm2_kernel(float* __restrict__ y) {
    int node = (blockIdx.x * 256 + threadIdx.x) >> 5;
    if (node >= N_NODES) return;
    int lane = threadIdx.x & 31;

    int beg = g_offsets[node];
    int end = g_offsets[node + 1];

    float4 acc = make_float4(0.f, 0.f, 0.f, 0.f);
    for (int j = beg; j < end; j++) {
        int2 e = __ldg(&g_edge[j]);
        float wv = __int_as_float(e.y);
        uint2 v = __ldg(&((const uint2*)(g_H2p + (size_t)e.x * (F_OUT / 2)))[lane]);
        float2 f0 = unpack_f16x2(v.x), f1 = unpack_f16x2(v.y);
        acc.x = fmaf(wv, f0.x, acc.x);
        acc.y = fmaf(wv, f0.y, acc.y);
        acc.z = fmaf(wv, f1.x, acc.z);
        acc.w = fmaf(wv, f1.y, acc.w);
    }
    ((float4*)(y + (size_t)node * F_OUT))[lane] = acc;
}

// ===========================================================================
// GEMM common: block 128x128, BK=16, 8 warps (2x4), warp tile 64x32,
// single fp16 MMA per fragment. Smem: As[m][kp] pitch 12, Bs[kp][n] pitch 136.
// Epilogue writes packed fp16 u32 (column-pair).
// ===========================================================================
#define AP 12
#define BP 136

struct GemmSmem {
    unsigned As[2][128 * AP];
    unsigned Bs[2][8 * BP];
};

__device__ __forceinline__ void mma_pass(float acc[4][4][4],
                                         const unsigned* As_p,
                                         const unsigned* Bs_p,
                                         int warp_m, int warp_n,
                                         int g, int tig) {
    unsigned b[4][2];
    #pragma unroll
    for (int nt = 0; nt < 4; nt++) {
        int cb = warp_n * 32 + nt * 8 + g;
        b[nt][0] = Bs_p[tig * BP + cb];
        b[nt][1] = Bs_p[(tig + 4) * BP + cb];
    }
    #pragma unroll
    for (int mt = 0; mt < 4; mt++) {
        int rb = warp_m * 64 + mt * 16 + g;
        unsigned a[4];
        a[0] = As_p[rb * AP + tig];
        a[1] = As_p[(rb + 8) * AP + tig];
        a[2] = As_p[rb * AP + tig + 4];
        a[3] = As_p[(rb + 8) * AP + tig + 4];
        #pragma unroll
        for (int nt = 0; nt < 4; nt++)
            mma_f16(acc[mt][nt], a, b[nt]);
    }
}

// Store packed fp16: each acc pair (c, c+1) -> one u32 at column-pair c/2.
__device__ __forceinline__ void gemm_epilogue_pack(float acc[4][4][4],
                                                   unsigned* __restrict__ Cp,
                                                   int row0, int col0, int M, int NP,
                                                   int warp_m, int warp_n,
                                                   int g, int tig) {
    #pragma unroll
    for (int mt = 0; mt < 4; mt++) {
        int r_lo = row0 + warp_m * 64 + mt * 16 + g;
        int r_hi = r_lo + 8;
        #pragma unroll
        for (int nt = 0; nt < 4; nt++) {
            int cp = (col0 + warp_n * 32 + nt * 8 + 2 * tig) >> 1;
            if (r_lo < M)
                Cp[(size_t)r_lo * NP + cp] = cvt_f16x2(acc[mt][nt][0], acc[mt][nt][1]);
            if (r_hi < M)
                Cp[(size_t)r_hi * NP + cp] = cvt_f16x2(acc[mt][nt][2], acc[mt][nt][3]);
        }
    }
}

// ---------------------------------------------------------------------------
// GEMM1: H0p = pack(X @ W1)  (A fp32 cvt in-loop, B pre-packed via cp.async)
// ---------------------------------------------------------------------------
__global__ __launch_bounds__(256, 2)
void gemm1_kernel(const float* __restrict__ A,
                  const unsigned* __restrict__ Bp,
                  unsigned* __restrict__ Cp, int M, int N, int K) {
    __shared__ __align__(16) GemmSmem sm;

    const int tid  = threadIdx.x;
    const int lane = tid & 31;
    const int warp = tid >> 5;
    const int g    = lane >> 2;
    const int tig  = lane & 3;
    const int warp_m = warp & 1;
    const int warp_n = warp >> 1;

    const int row0 = blockIdx.y * 128;
    const int col0 = blockIdx.x * 128;

    const int a_m0 = tid >> 2;
    const int a_kq = tid & 3;
    const int b_r  = tid >> 5;
    const int b_s  = (tid & 31) * 4;

    float acc[4][4][4];
    #pragma unroll
    for (int i = 0; i < 4; i++)
        #pragma unroll
        for (int j = 0; j < 4; j++)
            #pragma unroll
            for (int l = 0; l < 4; l++) acc[i][j][l] = 0.f;

    float4 a_reg[2];

    auto ldg_a = [&](int k0) {
        #pragma unroll
        for (int p = 0; p < 2; p++) {
            int gr = row0 + a_m0 + p * 64;
            a_reg[p] = (gr < M)
                ? *(const float4*)(A + (size_t)gr * K + k0 + a_kq * 4)
                : make_float4(0.f, 0.f, 0.f, 0.f);
        }
    };

    auto sts_a = [&](int s) {
        #pragma unroll
        for (int p = 0; p < 2; p++) {
            int m = a_m0 + p * 64;
            int off = m * AP + a_kq * 2;
            *(uint2*)&sm.As[s][off] =
                make_uint2(cvt_f16x2(a_reg[p].x, a_reg[p].y),
                           cvt_f16x2(a_reg[p].z, a_reg[p].w));
        }
    };

    auto cp_b = [&](int s, int t) {
        const unsigned* src = Bp + (size_t)(t * 8 + b_r) * N + col0 + b_s;
        cp_async16(smem_u32p(&sm.Bs[s][b_r * BP + b_s]), src, 16);
    };

    const int T = K / 16;
    ldg_a(0);
    cp_b(0, 0);
    CP_COMMIT();
    for (int t = 0; t < T; t++) {
        int s = t & 1;
        sts_a(s);
        if (t + 1 < T) ldg_a((t + 1) * 16);
        CP_WAIT_0();
        __syncthreads();
        if (t + 1 < T) { cp_b((t + 1) & 1, t + 1); CP_COMMIT(); }
        mma_pass(acc, sm.As[s], sm.Bs[s], warp_m, warp_n, g, tig);
        __syncthreads();
    }
    gemm_epilogue_pack(acc, Cp, row0, col0, M, N / 2, warp_m, warp_n, g, tig);
}

// ---------------------------------------------------------------------------
// GEMM2: H2p = pack(H1p @ W2)  (both sides pre-packed via cp.async)
// ---------------------------------------------------------------------------
__global__ __launch_bounds__(256, 2)
void gemm2_kernel(const unsigned* __restrict__ Ap,
                  const unsigned* __restrict__ Bp,
                  unsigned* __restrict__ Cp, int M, int N, int K) {
    __shared__ __align__(16) GemmSmem sm;

    const int tid  = threadIdx.x;
    const int lane = tid & 31;
    const int warp = tid >> 5;
    const int g    = lane >> 2;
    const int tig  = lane & 3;
    const int warp_m = warp & 1;
    const int warp_n = warp >> 1;

    const int row0 = blockIdx.y * 128;
    const int col0 = blockIdx.x * 128;
    const int KP = K / 2;

    const int a_m = tid >> 1;
    const int a_h = (tid & 1) * 4;
    const int b_r = tid >> 5;
    const int b_s = (tid & 31) * 4;

    float acc[4][4][4];
    #pragma unroll
    for (int i = 0; i < 4; i++)
        #pragma unroll
        for (int j = 0; j < 4; j++)
            #pragma unroll
            for (int l = 0; l < 4; l++) acc[i][j][l] = 0.f;

    auto cp_tile = [&](int s, int t) {
        int gr = row0 + a_m;
        int ok = (gr < M) ? 16 : 0;
        const unsigned* sa = Ap + (size_t)(gr < M ? gr : 0) * KP + t * 8 + a_h;
        cp_async16(smem_u32p(&sm.As[s][a_m * AP + a_h]), sa, ok);
        const unsigned* sb = Bp + (size_t)(t * 8 + b_r) * N + col0 + b_s;
        cp_async16(smem_u32p(&sm.Bs[s][b_r * BP + b_s]), sb, 16);
    };

    const int T = K / 16;
    cp_tile(0, 0);
    CP_COMMIT();
    for (int t = 0; t < T; t++) {
        int s = t & 1;
        CP_WAIT_0();
        __syncthreads();
        if (t + 1 < T) { cp_tile((t + 1) & 1, t + 1); CP_COMMIT(); }
        mma_pass(acc, sm.As[s], sm.Bs[s], warp_m, warp_n, g, tig);
        __syncthreads();
    }
    gemm_epilogue_pack(acc, Cp, row0, col0, M, N / 2, warp_m, warp_n, g, tig);
}

// ---------------------------------------------------------------------------
// Launch
// ---------------------------------------------------------------------------
extern "C" void kernel_launch(void* const* d_in, const int* in_sizes, int n_in,
                              void* d_out, int out_size) {
    const float* X    = (const float*)d_in[0];
    const int*   esrc = (const int*)  d_in[1];
    const int*   edst = (const int*)  d_in[2];
    const float* ew   = (const float*)d_in[3];
    const float* W1   = (const float*)d_in[4];
    const float* W2   = (const float*)d_in[5];
    float* out = (float*)d_out;

    unsigned *H0p, *H1p, *H2p, *W1p, *W2p;
    cudaGetSymbolAddress((void**)&H0p, g_H0p);
    cudaGetSymbolAddress((void**)&H1p, g_H1p);
    cudaGetSymbolAddress((void**)&H2p, g_H2p);
    cudaGetSymbolAddress((void**)&W1p, g_W1p);
    cudaGetSymbolAddress((void**)&W2p, g_W2p);

    const int T = 256;
    const int MB = (N_NODES + 127) / 128;
    const int node_blocks = (N_NODES + T - 1) / T;
    const int edge_blocks = (N_EDGES + T - 1) / T;
    const int spmm_blocks = (N_NODES * 32 + T - 1) / T;

    // ---- weight pre-pack (fp16)
    wpack_kernel<<<((F_IN / 2) * F_HID + T - 1) / T, T>>>(W1, W1p, F_IN, F_HID);
    wpack_kernel<<<((F_HID / 2) * F_OUT + T - 1) / T, T>>>(W2, W2p, F_HID, F_OUT);

    // ---- CSR build
    zero_deg_kernel<<<node_blocks, T>>>();
    hist_kernel<<<edge_blocks, T>>>(edst);
    scan_blocks_kernel<<<SCAN_BLOCKS, 1024>>>();
    add_off_kernel<<<node_blocks, T>>>();
    fill_kernel<<<edge_blocks, T>>>(esrc, edst, ew);

    // ---- layer 1: H0p = pack(X @ W1) ; H1p = pack(relu(spmm(H0p)))
    gemm1_kernel<<<dim3(F_HID / 128, MB), T>>>(X, W1p, H0p, N_NODES, F_HID, F_IN);
    spmm1_kernel<<<spmm_blocks, T>>>();

    // ---- layer 2: H2p = pack(H1p @ W2) ; out = spmm(H2p)
    gemm2_kernel<<<dim3(F_OUT / 128, MB), T>>>(H1p, W2p, H2p, N_NODES, F_OUT, F_HID);
    spmm2_kernel<<<spmm_blocks, T>>>(out);
}

// round 16
// speedup vs baseline: 1.8420x; 1.0997x over previous
#include <cuda_runtime.h>
#include <cuda_fp16.h>

#define N_NODES 50000
#define N_EDGES 800000
#define F_IN    512
#define F_HID   256
#define F_OUT   128

#define SCAN_BLOCKS 64           // 64 * 1024 >= N_NODES

// Scratch (all intermediates packed fp16 k-pairs: u32 j = features 2j, 2j+1)
__device__ unsigned g_H0p[(size_t)N_NODES * (F_HID / 2)];
__device__ unsigned g_H1p[(size_t)N_NODES * (F_HID / 2)];
__device__ unsigned g_H2p[(size_t)N_NODES * (F_OUT / 2)];
__device__ int      g_deg[N_NODES];          // zeroed by fill (prev call) / load-init
__device__ int      g_bsum[SCAN_BLOCKS];
__device__ int      g_bflag[SCAN_BLOCKS];    // reset by hist each call / load-init
__device__ int      g_offsets[N_NODES + 1];
__device__ int      g_cursor[N_NODES];
__device__ int2     g_edge[N_EDGES];         // {src, float_bits(w)} dst-sorted
__device__ unsigned g_W1p[(F_IN / 2) * F_HID];
__device__ unsigned g_W2p[(F_HID / 2) * F_OUT];

// ---------------------------------------------------------------------------
// helpers
// ---------------------------------------------------------------------------
__device__ __forceinline__ unsigned cvt_f16x2(float f0, float f1) {
    unsigned p;   // f0 -> low half (even k), f1 -> high half (odd k)
    asm("cvt.rn.f16x2.f32 %0, %1, %2;" : "=r"(p) : "f"(f1), "f"(f0));
    return p;
}

__device__ __forceinline__ float2 unpack_f16x2(unsigned p) {
    return __half22float2(*(__half2*)&p);
}

__device__ __forceinline__ void mma_f16(float c[4], const unsigned a[4],
                                        const unsigned b[2]) {
    asm volatile(
        "mma.sync.aligned.m16n8k16.row.col.f32.f16.f16.f32 "
        "{%0,%1,%2,%3}, {%4,%5,%6,%7}, {%8,%9}, {%0,%1,%2,%3};"
        : "+f"(c[0]), "+f"(c[1]), "+f"(c[2]), "+f"(c[3])
        : "r"(a[0]), "r"(a[1]), "r"(a[2]), "r"(a[3]), "r"(b[0]), "r"(b[1]));
}

__device__ __forceinline__ unsigned smem_u32p(const void* p) {
    return (unsigned)__cvta_generic_to_shared(p);
}

__device__ __forceinline__ void cp_async16(unsigned dst, const void* src, int src_bytes) {
    asm volatile("cp.async.ca.shared.global [%0], [%1], 16, %2;"
                 :: "r"(dst), "l"(src), "r"(src_bytes));
}
#define CP_COMMIT() asm volatile("cp.async.commit_group;")
#define CP_WAIT_0() asm volatile("cp.async.wait_group 0;")

// ---------------------------------------------------------------------------
// prep: pack both weight matrices (fp16 k-pair format) in one kernel
// ---------------------------------------------------------------------------
#define W1_ELEMS ((F_IN / 2) * F_HID)
#define W2_ELEMS ((F_HID / 2) * F_OUT)

__global__ void prep_kernel(const float* __restrict__ W1,
                            const float* __restrict__ W2) {
    int idx = blockIdx.x * 256 + threadIdx.x;
    if (idx < W1_ELEMS) {
        int kp = idx / F_HID, n = idx - kp * F_HID;
        g_W1p[idx] = cvt_f16x2(W1[(size_t)(2 * kp) * F_HID + n],
                               W1[(size_t)(2 * kp + 1) * F_HID + n]);
    } else {
        int j = idx - W1_ELEMS;
        if (j < W2_ELEMS) {
            int kp = j / F_OUT, n = j - kp * F_OUT;
            g_W2p[j] = cvt_f16x2(W2[(size_t)(2 * kp) * F_OUT + n],
                                 W2[(size_t)(2 * kp + 1) * F_OUT + n]);
        }
    }
}

// ---------------------------------------------------------------------------
// CSR build: hist (+bflag reset) -> lookback scan+offsets -> fill (+deg reset)
// ---------------------------------------------------------------------------
__global__ void hist_kernel(const int* __restrict__ dst) {
    int e = blockIdx.x * blockDim.x + threadIdx.x;
    if (e < SCAN_BLOCKS) g_bflag[e] = 0;
    if (e < N_EDGES) atomicAdd(&g_deg[dst[e]], 1);
}

// 64 co-resident blocks: local scan, publish total, parallel lookback poll.
__global__ __launch_bounds__(1024)
void scan_off_kernel() {
    __shared__ int sm[1024];
    __shared__ int pref_sm[SCAN_BLOCKS];
    __shared__ int s_pref;
    int tid = threadIdx.x, bid = blockIdx.x;
    int i = bid * 1024 + tid;
    int v = (i < N_NODES) ? g_deg[i] : 0;
    sm[tid] = v;
    __syncthreads();
    #pragma unroll
    for (int d = 1; d < 1024; d <<= 1) {
        int t = (tid >= d) ? sm[tid - d] : 0;
        __syncthreads();
        sm[tid] += t;
        __syncthreads();
    }
    // publish block total
    if (tid == 0) {
        g_bsum[bid] = sm[1023];
        __threadfence();
        atomicExch(&g_bflag[bid], 1);
    }
    // parallel lookback: thread j polls predecessor j
    if (tid < bid) {
        while (atomicAdd(&g_bflag[tid], 0) == 0) {}
        __threadfence();
        pref_sm[tid] = g_bsum[tid];
    } else if (tid < SCAN_BLOCKS) {
        pref_sm[tid] = 0;
    }
    __syncthreads();
    if (tid == 0) {
        int p = 0;
        #pragma unroll
        for (int j = 0; j < SCAN_BLOCKS; j++) p += pref_sm[j];
        s_pref = p;
    }
    __syncthreads();
    if (i < N_NODES) {
        int off = sm[tid] - v + s_pref;   // exclusive global prefix
        g_offsets[i] = off;
        g_cursor[i]  = off;
    }
    if (bid == 0 && tid == 0) g_offsets[N_NODES] = N_EDGES;
}

__global__ void fill_kernel(const int* __restrict__ src,
                            const int* __restrict__ dst,
                            const float* __restrict__ w) {
    int e = blockIdx.x * blockDim.x + threadIdx.x;
    if (e < N_NODES) g_deg[e] = 0;   // re-arm for next call (scan already consumed)
    if (e >= N_EDGES) return;
    int pos = atomicAdd(&g_cursor[dst[e]], 1);
    g_edge[pos] = make_int2(src[e], __float_as_int(w[e]));
}

// ---------------------------------------------------------------------------
// SpMM layer 1: H1p = pack(relu(spmm(H0p)))
// ---------------------------------------------------------------------------
__global__ __launch_bounds__(256)
void spmm1_kernel() {
    int node = (blockIdx.x * 256 + threadIdx.x) >> 5;
    if (node >= N_NODES) return;
    int lane = threadIdx.x & 31;

    int beg = g_offsets[node];
    int end = g_offsets[node + 1];

    float acc[8] = {};
    for (int j = beg; j < end; j++) {
        int2 e = __ldg(&g_edge[j]);
        float wv = __int_as_float(e.y);
        uint4 v = __ldg(&((const uint4*)(g_H0p + (size_t)e.x * (F_HID / 2)))[lane]);
        float2 f0 = unpack_f16x2(v.x), f1 = unpack_f16x2(v.y);
        float2 f2 = unpack_f16x2(v.z), f3 = unpack_f16x2(v.w);
        acc[0] = fmaf(wv, f0.x, acc[0]); acc[1] = fmaf(wv, f0.y, acc[1]);
        acc[2] = fmaf(wv, f1.x, acc[2]); acc[3] = fmaf(wv, f1.y, acc[3]);
        acc[4] = fmaf(wv, f2.x, acc[4]); acc[5] = fmaf(wv, f2.y, acc[5]);
        acc[6] = fmaf(wv, f3.x, acc[6]); acc[7] = fmaf(wv, f3.y, acc[7]);
    }
    #pragma unroll
    for (int i = 0; i < 8; i++) acc[i] = fmaxf(acc[i], 0.f);

    uint4 o;
    o.x = cvt_f16x2(acc[0], acc[1]);
    o.y = cvt_f16x2(acc[2], acc[3]);
    o.z = cvt_f16x2(acc[4], acc[5]);
    o.w = cvt_f16x2(acc[6], acc[7]);
    ((uint4*)(g_H1p + (size_t)node * (F_HID / 2)))[lane] = o;
}

// ---------------------------------------------------------------------------
// SpMM layer 2: out = spmm(H2p), fp32 out
// ---------------------------------------------------------------------------
__global__ __launch_bounds__(256)
void spmm2_kernel(float* __restrict__ y) {
    int node = (blockIdx.x * 256 + threadIdx.x) >> 5;
    if (node >= N_NODES) return;
    int lane = threadIdx.x & 31;

    int beg = g_offsets[node];
    int end = g_offsets[node + 1];

    float4 acc = make_float4(0.f, 0.f, 0.f, 0.f);
    for (int j = beg; j < end; j++) {
        int2 e = __ldg(&g_edge[j]);
        float wv = __int_as_float(e.y);
        uint2 v = __ldg(&((const uint2*)(g_H2p + (size_t)e.x * (F_OUT / 2)))[lane]);
        float2 f0 = unpack_f16x2(v.x), f1 = unpack_f16x2(v.y);
        acc.x = fmaf(wv, f0.x, acc.x);
        acc.y = fmaf(wv, f0.y, acc.y);
        acc.z = fmaf(wv, f1.x, acc.z);
        acc.w = fmaf(wv, f1.y, acc.w);
    }
    ((float4*)(y + (size_t)node * F_OUT))[lane] = acc;
}

// ===========================================================================
// GEMM (as Round 15): block 128x128, BK=16, 8 warps, warp tile 64x32,
// single fp16 MMA. As[m][kp] pitch 12, Bs[kp][n] pitch 136. Packed output.
// ===========================================================================
#define AP 12
#define BP 136

struct GemmSmem {
    unsigned As[2][128 * AP];
    unsigned Bs[2][8 * BP];
};

__device__ __forceinline__ void mma_pass(float acc[4][4][4],
                                         const unsigned* As_p,
                                         const unsigned* Bs_p,
                                         int warp_m, int warp_n,
                                         int g, int tig) {
    unsigned b[4][2];
    #pragma unroll
    for (int nt = 0; nt < 4; nt++) {
        int cb = warp_n * 32 + nt * 8 + g;
        b[nt][0] = Bs_p[tig * BP + cb];
        b[nt][1] = Bs_p[(tig + 4) * BP + cb];
    }
    #pragma unroll
    for (int mt = 0; mt < 4; mt++) {
        int rb = warp_m * 64 + mt * 16 + g;
        unsigned a[4];
        a[0] = As_p[rb * AP + tig];
        a[1] = As_p[(rb + 8) * AP + tig];
        a[2] = As_p[rb * AP + tig + 4];
        a[3] = As_p[(rb + 8) * AP + tig + 4];
        #pragma unroll
        for (int nt = 0; nt < 4; nt++)
            mma_f16(acc[mt][nt], a, b[nt]);
    }
}

__device__ __forceinline__ void gemm_epilogue_pack(float acc[4][4][4],
                                                   unsigned* __restrict__ Cp,
                                                   int row0, int col0, int M, int NP,
                                                   int warp_m, int warp_n,
                                                   int g, int tig) {
    #pragma unroll
    for (int mt = 0; mt < 4; mt++) {
        int r_lo = row0 + warp_m * 64 + mt * 16 + g;
        int r_hi = r_lo + 8;
        #pragma unroll
        for (int nt = 0; nt < 4; nt++) {
            int cp = (col0 + warp_n * 32 + nt * 8 + 2 * tig) >> 1;
            if (r_lo < M)
                Cp[(size_t)r_lo * NP + cp] = cvt_f16x2(acc[mt][nt][0], acc[mt][nt][1]);
            if (r_hi < M)
                Cp[(size_t)r_hi * NP + cp] = cvt_f16x2(acc[mt][nt][2], acc[mt][nt][3]);
        }
    }
}

__global__ __launch_bounds__(256, 2)
void gemm1_kernel(const float* __restrict__ A,
                  const unsigned* __restrict__ Bp,
                  unsigned* __restrict__ Cp, int M, int N, int K) {
    __shared__ __align__(16) GemmSmem sm;

    const int tid  = threadIdx.x;
    const int lane = tid & 31;
    const int warp = tid >> 5;
    const int g    = lane >> 2;
    const int tig  = lane & 3;
    const int warp_m = warp & 1;
    const int warp_n = warp >> 1;

    const int row0 = blockIdx.y * 128;
    const int col0 = blockIdx.x * 128;

    const int a_m0 = tid >> 2;
    const int a_kq = tid & 3;
    const int b_r  = tid >> 5;
    const int b_s  = (tid & 31) * 4;

    float acc[4][4][4];
    #pragma unroll
    for (int i = 0; i < 4; i++)
        #pragma unroll
        for (int j = 0; j < 4; j++)
            #pragma unroll
            for (int l = 0; l < 4; l++) acc[i][j][l] = 0.f;

    float4 a_reg[2];

    auto ldg_a = [&](int k0) {
        #pragma unroll
        for (int p = 0; p < 2; p++) {
            int gr = row0 + a_m0 + p * 64;
            a_reg[p] = (gr < M)
                ? *(const float4*)(A + (size_t)gr * K + k0 + a_kq * 4)
                : make_float4(0.f, 0.f, 0.f, 0.f);
        }
    };

    auto sts_a = [&](int s) {
        #pragma unroll
        for (int p = 0; p < 2; p++) {
            int m = a_m0 + p * 64;
            int off = m * AP + a_kq * 2;
            *(uint2*)&sm.As[s][off] =
                make_uint2(cvt_f16x2(a_reg[p].x, a_reg[p].y),
                           cvt_f16x2(a_reg[p].z, a_reg[p].w));
        }
    };

    auto cp_b = [&](int s, int t) {
        const unsigned* src = Bp + (size_t)(t * 8 + b_r) * N + col0 + b_s;
        cp_async16(smem_u32p(&sm.Bs[s][b_r * BP + b_s]), src, 16);
    };

    const int T = K / 16;
    ldg_a(0);
    cp_b(0, 0);
    CP_COMMIT();
    for (int t = 0; t < T; t++) {
        int s = t & 1;
        sts_a(s);
        if (t + 1 < T) ldg_a((t + 1) * 16);
        CP_WAIT_0();
        __syncthreads();
        if (t + 1 < T) { cp_b((t + 1) & 1, t + 1); CP_COMMIT(); }
        mma_pass(acc, sm.As[s], sm.Bs[s], warp_m, warp_n, g, tig);
        __syncthreads();
    }
    gemm_epilogue_pack(acc, Cp, row0, col0, M, N / 2, warp_m, warp_n, g, tig);
}

__global__ __launch_bounds__(256, 2)
void gemm2_kernel(const unsigned* __restrict__ Ap,
                  const unsigned* __restrict__ Bp,
                  unsigned* __restrict__ Cp, int M, int N, int K) {
    __shared__ __align__(16) GemmSmem sm;

    const int tid  = threadIdx.x;
    const int lane = tid & 31;
    const int warp = tid >> 5;
    const int g    = lane >> 2;
    const int tig  = lane & 3;
    const int warp_m = warp & 1;
    const int warp_n = warp >> 1;

    const int row0 = blockIdx.y * 128;
    const int col0 = blockIdx.x * 128;
    const int KP = K / 2;

    const int a_m = tid >> 1;
    const int a_h = (tid & 1) * 4;
    const int b_r = tid >> 5;
    const int b_s = (tid & 31) * 4;

    float acc[4][4][4];
    #pragma unroll
    for (int i = 0; i < 4; i++)
        #pragma unroll
        for (int j = 0; j < 4; j++)
            #pragma unroll
            for (int l = 0; l < 4; l++) acc[i][j][l] = 0.f;

    auto cp_tile = [&](int s, int t) {
        int gr = row0 + a_m;
        int ok = (gr < M) ? 16 : 0;
        const unsigned* sa = Ap + (size_t)(gr < M ? gr : 0) * KP + t * 8 + a_h;
        cp_async16(smem_u32p(&sm.As[s][a_m * AP + a_h]), sa, ok);
        const unsigned* sb = Bp + (size_t)(t * 8 + b_r) * N + col0 + b_s;
        cp_async16(smem_u32p(&sm.Bs[s][b_r * BP + b_s]), sb, 16);
    };

    const int T = K / 16;
    cp_tile(0, 0);
    CP_COMMIT();
    for (int t = 0; t < T; t++) {
        int s = t & 1;
        CP_WAIT_0();
        __syncthreads();
        if (t + 1 < T) { cp_tile((t + 1) & 1, t + 1); CP_COMMIT(); }
        mma_pass(acc, sm.As[s], sm.Bs[s], warp_m, warp_n, g, tig);
        __syncthreads();
    }
    gemm_epilogue_pack(acc, Cp, row0, col0, M, N / 2, warp_m, warp_n, g, tig);
}

// ---------------------------------------------------------------------------
// Launch — forked graph: CSR build on a side stream, overlapped with
// prep+GEMM1 on the main stream; joined before SpMM1.
// ---------------------------------------------------------------------------
extern "C" void kernel_launch(void* const* d_in, const int* in_sizes, int n_in,
                              void* d_out, int out_size) {
    const float* X    = (const float*)d_in[0];
    const int*   esrc = (const int*)  d_in[1];
    const int*   edst = (const int*)  d_in[2];
    const float* ew   = (const float*)d_in[3];
    const float* W1   = (const float*)d_in[4];
    const float* W2   = (const float*)d_in[5];
    float* out = (float*)d_out;

    unsigned *H0p, *H1p, *H2p, *W1p, *W2p;
    cudaGetSymbolAddress((void**)&H0p, g_H0p);
    cudaGetSymbolAddress((void**)&H1p, g_H1p);
    cudaGetSymbolAddress((void**)&H2p, g_H2p);
    cudaGetSymbolAddress((void**)&W1p, g_W1p);
    cudaGetSymbolAddress((void**)&W2p, g_W2p);

    // One-time resources (created on the first, non-captured correctness call)
    static cudaStream_t side = nullptr;
    static cudaEvent_t ev_fork = nullptr, ev_join = nullptr;
    if (side == nullptr) {
        cudaStreamCreateWithFlags(&side, cudaStreamNonBlocking);
        cudaEventCreateWithFlags(&ev_fork, cudaEventDisableTiming);
        cudaEventCreateWithFlags(&ev_join, cudaEventDisableTiming);
    }

    const int T = 256;
    const int MB = (N_NODES + 127) / 128;
    const int edge_blocks = (N_EDGES + T - 1) / T;
    const int spmm_blocks = (N_NODES * 32 + T - 1) / T;
    const int prep_blocks = (W1_ELEMS + W2_ELEMS + T - 1) / T;

    // ---- fork: CSR build on side stream
    cudaEventRecord(ev_fork, 0);
    cudaStreamWaitEvent(side, ev_fork, 0);
    hist_kernel<<<edge_blocks, T, 0, side>>>(edst);
    scan_off_kernel<<<SCAN_BLOCKS, 1024, 0, side>>>();
    fill_kernel<<<edge_blocks, T, 0, side>>>(esrc, edst, ew);
    cudaEventRecord(ev_join, side);

    // ---- main stream: weight pack + GEMM1
    prep_kernel<<<prep_blocks, T>>>(W1, W2);
    gemm1_kernel<<<dim3(F_HID / 128, MB), T>>>(X, W1p, H0p, N_NODES, F_HID, F_IN);

    // ---- join, then SpMM1 -> GEMM2 -> SpMM2
    cudaStreamWaitEvent(0, ev_join, 0);
    spmm1_kernel<<<spmm_blocks, T>>>();
    gemm2_kernel<<<dim3(F_OUT / 128, MB), T>>>(H1p, W2p, H2p, N_NODES, F_OUT, F_HID);
    spmm2_kernel<<<spmm_blocks, T>>>(out);
}